// round 1
// baseline (speedup 1.0000x reference)
#include <cuda_runtime.h>
#include <cuda_bf16.h>

// Problem constants
#define BB   16
#define CC   256
#define HH   32
#define WW   32
#define HWN  1024               // H*W
#define NTOK 16384              // B*H*W
#define VN   8192               // vocab

// Main-kernel tiling
#define BM   64                 // tokens per CTA
#define BV   128                // codes per v-tile
#define BK   32                 // K chunk
#define MAIN_SMEM_FLOATS (CC*BM + BK*BV)   // 16384 + 4096 = 20480 floats = 80 KB

// Scratch (device globals: allocation-free)
__device__ float g_xf[NTOK * CC];   // x transposed to [N][C]
__device__ float g_esq[VN];         // ||e_v||^2
__device__ int   g_idx[NTOK];       // argmin index per token

// ---------------------------------------------------------------------------
// helpers: packed f32x2 (Blackwell FFMA2 path)
// ---------------------------------------------------------------------------
static __device__ __forceinline__ unsigned long long dupf(float v) {
    unsigned long long r;
    asm("mov.b64 %0, {%1, %1};" : "=l"(r) : "f"(v));
    return r;
}
static __device__ __forceinline__ void fma2(unsigned long long& d,
                                            unsigned long long a,
                                            unsigned long long b) {
    asm("fma.rn.f32x2 %0, %1, %2, %0;" : "+l"(d) : "l"(a), "l"(b));
}
static __device__ __forceinline__ float2 ull2f2(unsigned long long u) {
    float2 f;
    asm("mov.b64 {%0, %1}, %2;" : "=f"(f.x), "=f"(f.y) : "l"(u));
    return f;
}

// ---------------------------------------------------------------------------
// Kernel 1: transpose x [B,C,HW] -> g_xf [N=B*HW][C]   (coalesced both sides)
// ---------------------------------------------------------------------------
__global__ void vq_transpose(const float* __restrict__ x) {
    __shared__ float t[32][33];
    const int b   = blockIdx.z;
    const int c0  = blockIdx.y * 32;
    const int hw0 = blockIdx.x * 32;
    const int tx = threadIdx.x, ty = threadIdx.y;   // (32,8)
#pragma unroll
    for (int i = 0; i < 4; i++) {
        int c = c0 + ty + i * 8;
        t[ty + i * 8][tx] = x[((size_t)(b * CC + c) << 10) + hw0 + tx];
    }
    __syncthreads();
#pragma unroll
    for (int i = 0; i < 4; i++) {
        int hw = hw0 + ty + i * 8;
        g_xf[(size_t)(b * HWN + hw) * CC + c0 + tx] = t[tx][ty + i * 8];
    }
}

// ---------------------------------------------------------------------------
// Kernel 2: ||e_v||^2 with fp64 accumulation (max accuracy vs reference)
// ---------------------------------------------------------------------------
__global__ void vq_esq(const float* __restrict__ cb) {
    const int v    = blockIdx.x * 8 + (threadIdx.x >> 5);
    const int lane = threadIdx.x & 31;
    const float* r = cb + (size_t)v * CC;
    float4 a = *(const float4*)(r + lane * 4);
    float4 b = *(const float4*)(r + 128 + lane * 4);
    double s = (double)a.x * a.x + (double)a.y * a.y + (double)a.z * a.z + (double)a.w * a.w
             + (double)b.x * b.x + (double)b.y * b.y + (double)b.z * b.z + (double)b.w * b.w;
#pragma unroll
    for (int off = 16; off > 0; off >>= 1)
        s += __shfl_xor_sync(0xffffffffu, s, off);
    if (lane == 0) g_esq[v] = (float)s;
}

// ---------------------------------------------------------------------------
// Kernel 3: fused distance GEMM + argmin.
// CTA: 64 tokens x (loop over all V in 128-code tiles). 256 threads.
// Thread tile: 8 tokens (4 packed f32x2 pairs) x 4 codes = 16 FFMA2 / k-step.
// warp <-> one 8-token group (ty): x-frag is warp-uniform (smem broadcast),
// final argmin reduction is a pure warp shuffle.
// ---------------------------------------------------------------------------
__global__ __launch_bounds__(256, 2)
void vq_main(const float* __restrict__ cb) {
    extern __shared__ float sm[];
    float* xs = sm;              // [CC][BM] : full x tile, K-major transposed
    float* es = sm + CC * BM;    // [BK][BV] : codebook K-chunk, transposed

    const int tid = threadIdx.x;
    const int tx  = tid & 31;    // code group (lane): codes tx*4..tx*4+3 of tile
    const int ty  = tid >> 5;    // token group (warp): tokens ty*8..ty*8+7
    const int n0  = blockIdx.x * BM;

    // ---- load full x tile, transposed: xs[c][m] = xf[n0+m][c] ----
    {
        const int m  = tid & 63;
        const int cg = tid >> 6;           // 0..3 -> 64 channels each
        const float* src = g_xf + (size_t)(n0 + m) * CC + cg * 64;
#pragma unroll
        for (int q = 0; q < 16; q++) {
            float4 v = *(const float4*)(src + q * 4);
            int c = cg * 64 + q * 4;
            xs[(c + 0) * BM + m] = v.x;
            xs[(c + 1) * BM + m] = v.y;
            xs[(c + 2) * BM + m] = v.z;
            xs[(c + 3) * BM + m] = v.w;
        }
    }
    __syncthreads();

    float best[8];
    int   bidx[8];
#pragma unroll
    for (int t = 0; t < 8; t++) { best[t] = 3.4e38f; bidx[t] = 0; }

    for (int v0 = 0; v0 < VN; v0 += BV) {
        unsigned long long acc[4][4];
#pragma unroll
        for (int p = 0; p < 4; p++)
#pragma unroll
            for (int j = 0; j < 4; j++) acc[p][j] = 0ull;

        for (int kt = 0; kt < CC; kt += BK) {
            // load es[kk][j] = cb[(v0+j)][kt+kk]
            {
                const int j  = tid & 127;
                const int kg = tid >> 7;    // 0..1
                const float* src = cb + (size_t)(v0 + j) * CC + kt + kg * 16;
#pragma unroll
                for (int q = 0; q < 4; q++) {
                    float4 v = *(const float4*)(src + q * 4);
                    int kk = kg * 16 + q * 4;
                    es[(kk + 0) * BV + j] = v.x;
                    es[(kk + 1) * BV + j] = v.y;
                    es[(kk + 2) * BV + j] = v.z;
                    es[(kk + 3) * BV + j] = v.w;
                }
            }
            __syncthreads();

#pragma unroll
            for (int kk = 0; kk < BK; kk++) {
                const float* xp = xs + (kt + kk) * BM + (ty << 3);
                ulonglong2 xa = *(const ulonglong2*)xp;        // tokens 0,1 | 2,3
                ulonglong2 xb = *(const ulonglong2*)(xp + 4);  // tokens 4,5 | 6,7
                const float4 ef = *(const float4*)(es + kk * BV + (tx << 2));
                unsigned long long e0 = dupf(ef.x), e1 = dupf(ef.y),
                                   e2 = dupf(ef.z), e3 = dupf(ef.w);
                fma2(acc[0][0], xa.x, e0); fma2(acc[0][1], xa.x, e1);
                fma2(acc[0][2], xa.x, e2); fma2(acc[0][3], xa.x, e3);
                fma2(acc[1][0], xa.y, e0); fma2(acc[1][1], xa.y, e1);
                fma2(acc[1][2], xa.y, e2); fma2(acc[1][3], xa.y, e3);
                fma2(acc[2][0], xb.x, e0); fma2(acc[2][1], xb.x, e1);
                fma2(acc[2][2], xb.x, e2); fma2(acc[2][3], xb.x, e3);
                fma2(acc[3][0], xb.y, e0); fma2(acc[3][1], xb.y, e1);
                fma2(acc[3][2], xb.y, e2); fma2(acc[3][3], xb.y, e3);
            }
            __syncthreads();
        }

        // epilogue: dist = ||e||^2 - 2*dot  (x^2 term is per-token constant)
        const float4 q4 = *(const float4*)(g_esq + v0 + (tx << 2));
        float eq[4] = {q4.x, q4.y, q4.z, q4.w};
#pragma unroll
        for (int p = 0; p < 4; p++) {
#pragma unroll
            for (int j = 0; j < 4; j++) {
                float2 a = ull2f2(acc[p][j]);
                const int code = v0 + (tx << 2) + j;
                float d0 = fmaf(-2.0f, a.x, eq[j]);
                float d1 = fmaf(-2.0f, a.y, eq[j]);
                if (d0 < best[2 * p])     { best[2 * p]     = d0; bidx[2 * p]     = code; }
                if (d1 < best[2 * p + 1]) { best[2 * p + 1] = d1; bidx[2 * p + 1] = code; }
            }
        }
    }

    // final: reduce (dist, idx) across the 32 lanes of the warp per token;
    // ties -> lowest index (matches jnp.argmin first-occurrence).
#pragma unroll
    for (int t = 0; t < 8; t++) {
        float d = best[t];
        int   ix = bidx[t];
#pragma unroll
        for (int off = 16; off > 0; off >>= 1) {
            float d2 = __shfl_xor_sync(0xffffffffu, d, off);
            int   i2 = __shfl_xor_sync(0xffffffffu, ix, off);
            if (d2 < d || (d2 == d && i2 < ix)) { d = d2; ix = i2; }
        }
        if (tx == 0) g_idx[n0 + (ty << 3) + t] = ix;
    }
}

// ---------------------------------------------------------------------------
// Kernel 4: gather + transpose back: out[b][c][hw] = cb[idx[n]][c]
// ---------------------------------------------------------------------------
__global__ void vq_gather(const float* __restrict__ cb, float* __restrict__ out) {
    __shared__ float t[32][33];
    const int b   = blockIdx.z;
    const int c0  = blockIdx.y * 32;
    const int hw0 = blockIdx.x * 32;
    const int tx = threadIdx.x, ty = threadIdx.y;   // (32,8)
#pragma unroll
    for (int i = 0; i < 4; i++) {
        int row  = ty + i * 8;                       // token within tile
        int code = g_idx[b * HWN + hw0 + row];
        t[row][tx] = cb[(size_t)code * CC + c0 + tx];
    }
    __syncthreads();
#pragma unroll
    for (int i = 0; i < 4; i++) {
        int c = c0 + ty + i * 8;
        out[((size_t)(b * CC + c) << 10) + hw0 + tx] = t[tx][ty + i * 8];
    }
}

// ---------------------------------------------------------------------------
extern "C" void kernel_launch(void* const* d_in, const int* in_sizes, int n_in,
                              void* d_out, int out_size) {
    const float* x  = (const float*)d_in[0];   // [B,C,H,W]
    const float* cb = (const float*)d_in[1];   // [V,C]
    float* out = (float*)d_out;                // [B,C,H,W]

    cudaFuncSetAttribute(vq_main, cudaFuncAttributeMaxDynamicSharedMemorySize,
                         MAIN_SMEM_FLOATS * (int)sizeof(float));

    vq_transpose<<<dim3(HWN / 32, CC / 32, BB), dim3(32, 8)>>>(x);
    vq_esq<<<VN / 8, 256>>>(cb);
    vq_main<<<NTOK / BM, 256, MAIN_SMEM_FLOATS * sizeof(float)>>>(cb);
    vq_gather<<<dim3(HWN / 32, CC / 32, BB), dim3(32, 8)>>>(cb, out);
}

// round 4
// speedup vs baseline: 3.2722x; 3.2722x over previous
#include <cuda_runtime.h>
#include <cuda_bf16.h>
#include <cstdint>

// ---------------- problem constants ----------------
#define BB   16
#define CC   256
#define HWN  1024
#define NTOK 16384
#define VN   8192

// ---------------- GEMM tiling (mma.sync path, sm_100-base safe) ----------
#define MT 128              // tokens per CTA
#define VT 128              // codes per CTA
#define KCH 32              // K per chunk
#define NCHUNK (CC/KCH)     // 8
#define ASTR 80             // smem row stride bytes (32 bf16 + 8 pad)
#define ABUF (128*ASTR)     // 10240 bytes per A/B buffer
#define SST 136             // stage stride in bf16 elements (272B rows)

// smem layout (bytes): [0,512) esq, [512, 512+2*ABUF) A bufs, then B bufs
#define SM_SE 0
#define SM_A  512
#define SM_B  (512 + 2*ABUF)
#define SM_DYN (512 + 4*ABUF)      // 41472
// stage (128 x SST bf16 = 34816B) aliases the A/B buffers at SM_A

// ---------------- device scratch (allocation-free) ----------------
__device__ float          g_xf[NTOK * CC];            // x fp32 [N][C]
__device__ __nv_bfloat16  g_xa[NTOK * CC];            // x bf16
__device__ __nv_bfloat16  g_cbb[VN * CC];             // codebook bf16
__device__ __nv_bfloat16  g_dots[(size_t)NTOK * VN];  // approx dots bf16
__device__ float          g_esq[VN];
__device__ unsigned long long g_best[NTOK];           // (distkey<<32)|idx
__device__ int            g_idx[NTOK];

// ---------------- PTX helpers ----------------
static __device__ __forceinline__ uint32_t smem_u32(const void* p) {
    uint32_t a;
    asm("{ .reg .u64 t; cvta.to.shared.u64 t, %1; cvt.u32.u64 %0, t; }" : "=r"(a) : "l"(p));
    return a;
}
static __device__ __forceinline__ void cp16(uint32_t dst, const void* src) {
    asm volatile("cp.async.cg.shared.global [%0], [%1], 16;" :: "r"(dst), "l"(src));
}
#define CP_COMMIT() asm volatile("cp.async.commit_group;" ::: "memory")
#define CP_WAIT(n)  asm volatile("cp.async.wait_group %0;" :: "n"(n) : "memory")

static __device__ __forceinline__ void ldsm4(uint32_t* r, uint32_t addr) {
    asm volatile("ldmatrix.sync.aligned.m8n8.x4.shared.b16 {%0,%1,%2,%3}, [%4];"
        : "=r"(r[0]), "=r"(r[1]), "=r"(r[2]), "=r"(r[3]) : "r"(addr));
}
static __device__ __forceinline__ void mma16816(float* d, const uint32_t* a,
                                                uint32_t b0, uint32_t b1) {
    asm volatile("mma.sync.aligned.m16n8k16.row.col.f32.bf16.bf16.f32 "
        "{%0,%1,%2,%3}, {%4,%5,%6,%7}, {%8,%9}, {%0,%1,%2,%3};"
        : "+f"(d[0]), "+f"(d[1]), "+f"(d[2]), "+f"(d[3])
        : "r"(a[0]), "r"(a[1]), "r"(a[2]), "r"(a[3]), "r"(b0), "r"(b1));
}

// ---------------------------------------------------------------------------
// K1: transpose x [B,C,HW] -> g_xf/g_xa [N][C]
// ---------------------------------------------------------------------------
__global__ void vq_transpose(const float* __restrict__ x) {
    __shared__ float t[32][33];
    const int b = blockIdx.z, c0 = blockIdx.y * 32, hw0 = blockIdx.x * 32;
    const int tx = threadIdx.x, ty = threadIdx.y;
#pragma unroll
    for (int i = 0; i < 4; i++) {
        int c = c0 + ty + i * 8;
        t[ty + i * 8][tx] = x[((size_t)(b * CC + c) << 10) + hw0 + tx];
    }
    __syncthreads();
#pragma unroll
    for (int i = 0; i < 4; i++) {
        int hw = hw0 + ty + i * 8;
        float v = t[tx][ty + i * 8];
        size_t o = (size_t)(b * HWN + hw) * CC + c0 + tx;
        g_xf[o] = v;
        g_xa[o] = __float2bfloat16(v);
    }
}

// ---------------------------------------------------------------------------
// K2: prep: esq (fp64-acc), codebook bf16, g_best init
// ---------------------------------------------------------------------------
__global__ void vq_prep(const float* __restrict__ cb) {
    const int gid = blockIdx.x * 256 + threadIdx.x;
    if (gid < NTOK) g_best[gid] = 0xFFFFFFFFFFFFFFFFull;
    const int v = blockIdx.x * 8 + (threadIdx.x >> 5);
    const int lane = threadIdx.x & 31;
    const float* r = cb + (size_t)v * CC;
    float4 a = *(const float4*)(r + lane * 4);
    float4 b = *(const float4*)(r + 128 + lane * 4);
    __nv_bfloat16* o = g_cbb + (size_t)v * CC;
    o[lane * 4 + 0] = __float2bfloat16(a.x);
    o[lane * 4 + 1] = __float2bfloat16(a.y);
    o[lane * 4 + 2] = __float2bfloat16(a.z);
    o[lane * 4 + 3] = __float2bfloat16(a.w);
    o[128 + lane * 4 + 0] = __float2bfloat16(b.x);
    o[128 + lane * 4 + 1] = __float2bfloat16(b.y);
    o[128 + lane * 4 + 2] = __float2bfloat16(b.z);
    o[128 + lane * 4 + 3] = __float2bfloat16(b.w);
    double s = (double)a.x * a.x + (double)a.y * a.y + (double)a.z * a.z + (double)a.w * a.w
             + (double)b.x * b.x + (double)b.y * b.y + (double)b.z * b.z + (double)b.w * b.w;
#pragma unroll
    for (int off = 16; off > 0; off >>= 1)
        s += __shfl_xor_sync(0xffffffffu, s, off);
    if (lane == 0) g_esq[v] = (float)s;
}

// ---------------------------------------------------------------------------
// K3: bf16 mma.sync GEMM (128x128 tile) + approx-argmin + bf16 dot dump
// ---------------------------------------------------------------------------
__global__ void __launch_bounds__(256) vq_gemm() {
    extern __shared__ char smem[];
    const uint32_t sb = smem_u32(smem);
    float* se = (float*)(smem + SM_SE);

    const int tid  = threadIdx.x;
    const int wid  = tid >> 5;
    const int lane = tid & 31;
    const int n0 = blockIdx.x * MT;
    const int v0 = blockIdx.y * VT;

    if (tid < VT) se[tid] = g_esq[v0 + tid];

    const __nv_bfloat16* asrc = g_xa  + (size_t)n0 * CC;
    const __nv_bfloat16* bsrc = g_cbb + (size_t)v0 * CC;

    // ---- async tile loader: chunk kc -> buffer (kc&1) ----
    auto load_chunk = [&](int kc, int buf) {
        const uint32_t sa = sb + SM_A + buf * ABUF;
        const uint32_t sbb = sb + SM_B + buf * ABUF;
#pragma unroll
        for (int i = 0; i < 2; i++) {
            int s = tid + 256 * i;          // 0..511
            int row = s >> 2, c16 = s & 3;  // 16B segment of 64B row
            cp16(sa  + row * ASTR + c16 * 16, asrc + (size_t)row * CC + kc * KCH + c16 * 8);
            cp16(sbb + row * ASTR + c16 * 16, bsrc + (size_t)row * CC + kc * KCH + c16 * 8);
        }
        CP_COMMIT();
    };

    // warp tiling: 4x2 warps, warp tile 32 rows x 64 cols
    const int warp_r = (wid & 3) * 32;
    const int warp_c = (wid >> 2) * 64;

    // per-thread ldmatrix base offsets (bytes, within a buffer)
    const uint32_t aoff = (uint32_t)((warp_r + (lane & 15)) * ASTR + (lane >> 4) * 16);
    const uint32_t boff = (uint32_t)((warp_c + (lane & 7) + ((lane >> 4) << 3)) * ASTR
                                     + ((lane >> 3) & 1) * 16);

    float acc[2][8][4];
#pragma unroll
    for (int mb = 0; mb < 2; mb++)
#pragma unroll
        for (int nb = 0; nb < 8; nb++)
#pragma unroll
            for (int q = 0; q < 4; q++) acc[mb][nb][q] = 0.0f;

    load_chunk(0, 0);

    for (int kc = 0; kc < NCHUNK; kc++) {
        if (kc + 1 < NCHUNK) load_chunk(kc + 1, (kc + 1) & 1);
        if (kc + 1 < NCHUNK) { CP_WAIT(1); } else { CP_WAIT(0); }
        __syncthreads();

        const uint32_t abase = sb + SM_A + (kc & 1) * ABUF + aoff;
        const uint32_t bbase = sb + SM_B + (kc & 1) * ABUF + boff;
#pragma unroll
        for (int ks = 0; ks < 2; ks++) {
            uint32_t af[2][4];
            ldsm4(af[0], abase + ks * 32);
            ldsm4(af[1], abase + 16 * ASTR + ks * 32);
            uint32_t bfr[4][4];
#pragma unroll
            for (int p = 0; p < 4; p++)
                ldsm4(bfr[p], bbase + p * 16 * ASTR + ks * 32);
#pragma unroll
            for (int mb = 0; mb < 2; mb++)
#pragma unroll
                for (int p = 0; p < 4; p++) {
                    mma16816(acc[mb][2 * p],     af[mb], bfr[p][0], bfr[p][1]);
                    mma16816(acc[mb][2 * p + 1], af[mb], bfr[p][2], bfr[p][3]);
                }
        }
        __syncthreads();
    }

    // ---- stage accums to smem as bf16 dots (stride SST kills conflicts) ----
    __nv_bfloat162* stage = (__nv_bfloat162*)(smem + SM_A);
#pragma unroll
    for (int mb = 0; mb < 2; mb++)
#pragma unroll
        for (int nb = 0; nb < 8; nb++) {
            int r0 = warp_r + mb * 16 + (lane >> 2);
            int c0 = warp_c + nb * 8 + (lane & 3) * 2;
            stage[(r0 * SST + c0) >> 1]       = __floats2bfloat162_rn(acc[mb][nb][0], acc[mb][nb][1]);
            stage[((r0 + 8) * SST + c0) >> 1] = __floats2bfloat162_rn(acc[mb][nb][2], acc[mb][nb][3]);
        }
    __syncthreads();

    // ---- per-row min + coalesced dump. warp w -> rows w*16..w*16+15 ----
    const __nv_bfloat16* stg = (const __nv_bfloat16*)(smem + SM_A);
#pragma unroll
    for (int r16 = 0; r16 < 16; r16++) {
        const int row = wid * 16 + r16;
        uint2 raw = *(const uint2*)(stg + row * SST + lane * 4);
        float2 f0 = __bfloat1622float2(*(__nv_bfloat162*)&raw.x);
        float2 f1 = __bfloat1622float2(*(__nv_bfloat162*)&raw.y);
        const int col = lane * 4;
        float d0 = fmaf(-2.0f, f0.x, se[col]);
        float d1 = fmaf(-2.0f, f0.y, se[col + 1]);
        float d2 = fmaf(-2.0f, f1.x, se[col + 2]);
        float d3 = fmaf(-2.0f, f1.y, se[col + 3]);
        float bd = d0; int bi = v0 + col;
        if (d1 < bd) { bd = d1; bi = v0 + col + 1; }
        if (d2 < bd) { bd = d2; bi = v0 + col + 2; }
        if (d3 < bd) { bd = d3; bi = v0 + col + 3; }
#pragma unroll
        for (int off = 16; off > 0; off >>= 1) {
            float od = __shfl_xor_sync(0xffffffffu, bd, off);
            int   oi = __shfl_xor_sync(0xffffffffu, bi, off);
            if (od < bd || (od == bd && oi < bi)) { bd = od; bi = oi; }
        }
        if (lane == 0) {
            uint32_t u = __float_as_uint(bd);
            uint32_t key = (u & 0x80000000u) ? ~u : (u ^ 0x80000000u);
            atomicMin(&g_best[n0 + row],
                      ((unsigned long long)key << 32) | (uint32_t)bi);
        }
        *(uint2*)(g_dots + (size_t)(n0 + row) * VN + v0 + lane * 4) = raw;
    }
}

// ---------------------------------------------------------------------------
// K4: scan approx dists, exact fp32 rescore of candidates within margin
// ---------------------------------------------------------------------------
#define MARGIN 6.0f
__global__ void __launch_bounds__(256) vq_scan(const float* __restrict__ cb) {
    __shared__ float se[VN];
    const int tid = threadIdx.x;
    {
        float4* d4 = (float4*)se;
        const float4* s4 = (const float4*)g_esq;
        for (int i = tid; i < VN / 4; i += 256) d4[i] = s4[i];
    }
    __syncthreads();

    const int wid = tid >> 5, lane = tid & 31;
    const int n = blockIdx.x * 8 + wid;

    unsigned long long bk = g_best[n];
    uint32_t key = (uint32_t)(bk >> 32);
    float minA = (key & 0x80000000u) ? __uint_as_float(key ^ 0x80000000u)
                                     : __uint_as_float(~key);
    const float thr = minA + MARGIN;

    float xr[8];
    {
        const float4* xp = (const float4*)(g_xf + (size_t)n * CC + lane * 8);
        float4 a = xp[0], b = xp[1];
        xr[0] = a.x; xr[1] = a.y; xr[2] = a.z; xr[3] = a.w;
        xr[4] = b.x; xr[5] = b.y; xr[6] = b.z; xr[7] = b.w;
    }

    float bestd = 3.4e38f;
    int   bestv = 0x7fffffff;
    const uint4* drow = (const uint4*)(g_dots + (size_t)n * VN);

    for (int it = 0; it < 32; it++) {
        uint4 q = drow[it * 32 + lane];
        const int vbase = it * 256 + lane * 8;
        float dd[8];
        {
            float2 f;
            f = __bfloat1622float2(*(__nv_bfloat162*)&q.x); dd[0] = f.x; dd[1] = f.y;
            f = __bfloat1622float2(*(__nv_bfloat162*)&q.y); dd[2] = f.x; dd[3] = f.y;
            f = __bfloat1622float2(*(__nv_bfloat162*)&q.z); dd[4] = f.x; dd[5] = f.y;
            f = __bfloat1622float2(*(__nv_bfloat162*)&q.w); dd[6] = f.x; dd[7] = f.y;
        }
#pragma unroll
        for (int j = 0; j < 8; j++) {
            float dist = fmaf(-2.0f, dd[j], se[vbase + j]);
            unsigned bal = __ballot_sync(0xffffffffu, dist <= thr);
            while (bal) {
                int src = __ffs(bal) - 1;
                bal &= bal - 1;
                int vc = __shfl_sync(0xffffffffu, vbase, src) + j;
                // exact fp32 rescore (warp-distributed dot)
                const float4* ep = (const float4*)(cb + (size_t)vc * CC + lane * 8);
                float4 ea = ep[0], eb = ep[1];
                float s = xr[0] * ea.x;
                s = fmaf(xr[1], ea.y, s); s = fmaf(xr[2], ea.z, s); s = fmaf(xr[3], ea.w, s);
                s = fmaf(xr[4], eb.x, s); s = fmaf(xr[5], eb.y, s);
                s = fmaf(xr[6], eb.z, s); s = fmaf(xr[7], eb.w, s);
#pragma unroll
                for (int off = 16; off > 0; off >>= 1)
                    s += __shfl_xor_sync(0xffffffffu, s, off);
                float d = fmaf(-2.0f, s, se[vc]);
                if (d < bestd || (d == bestd && vc < bestv)) { bestd = d; bestv = vc; }
            }
        }
    }
    if (lane == 0) g_idx[n] = bestv;
}

// ---------------------------------------------------------------------------
// K5: gather + transpose back
// ---------------------------------------------------------------------------
__global__ void vq_gather(const float* __restrict__ cb, float* __restrict__ out) {
    __shared__ float t[32][33];
    const int b = blockIdx.z, c0 = blockIdx.y * 32, hw0 = blockIdx.x * 32;
    const int tx = threadIdx.x, ty = threadIdx.y;
#pragma unroll
    for (int i = 0; i < 4; i++) {
        int row = ty + i * 8;
        int code = g_idx[b * HWN + hw0 + row];
        t[row][tx] = cb[(size_t)code * CC + c0 + tx];
    }
    __syncthreads();
#pragma unroll
    for (int i = 0; i < 4; i++) {
        int c = c0 + ty + i * 8;
        out[((size_t)(b * CC + c) << 10) + hw0 + tx] = t[tx][ty + i * 8];
    }
}

// ---------------------------------------------------------------------------
extern "C" void kernel_launch(void* const* d_in, const int* in_sizes, int n_in,
                              void* d_out, int out_size) {
    const float* x  = (const float*)d_in[0];
    const float* cb = (const float*)d_in[1];
    float* out = (float*)d_out;

    cudaFuncSetAttribute(vq_gemm, cudaFuncAttributeMaxDynamicSharedMemorySize, SM_DYN);

    vq_transpose<<<dim3(HWN / 32, CC / 32, BB), dim3(32, 8)>>>(x);
    vq_prep<<<VN / 8, 256>>>(cb);
    vq_gemm<<<dim3(NTOK / MT, VN / VT), 256, SM_DYN>>>();
    vq_scan<<<NTOK / 8, 256>>>(cb);
    vq_gather<<<dim3(HWN / 32, CC / 32, BB), dim3(32, 8)>>>(cb, out);
}

// round 6
// speedup vs baseline: 6.1345x; 1.8747x over previous
#include <cuda_runtime.h>
#include <cuda_bf16.h>
#include <cuda_fp16.h>
#include <cstdint>

// ---------------- problem constants ----------------
#define BB   16
#define CC   256
#define HWN  1024
#define NTOK 16384
#define VN   8192
#define NTILE (VN/128)      // 64 v-tiles per token

// ---------------- GEMM tiling (mma.sync path, sm_100-base safe) ----------
#define MT 128              // tokens per CTA
#define VT 128              // codes per CTA
#define KCH 32              // K per chunk
#define NCHUNK (CC/KCH)     // 8
#define ASTR 80             // smem row stride bytes (32 bf16 + 8 pad)
#define ABUF (128*ASTR)     // 10240 bytes per A/B buffer
#define SST 136             // stage stride in half elements (272B rows)

// smem layout (bytes): [0,512) esq, [512, 512+2*ABUF) A bufs, then B bufs
#define SM_SE 0
#define SM_A  512
#define SM_B  (512 + 2*ABUF)
#define SM_DYN (512 + 4*ABUF)      // 41472
// epilogue stage (128 x 272B = 34816B) aliases the A/B buffers at SM_A

// ---------------- device scratch (allocation-free) ----------------
__device__ float   g_xf[NTOK * CC];            // x fp32 [N][C]
__device__ __nv_bfloat16 g_xa[NTOK * CC];      // x bf16
__device__ __nv_bfloat16 g_cbb[VN * CC];       // codebook bf16
__device__ __half  g_dist[(size_t)NTOK * VN];  // approx dists fp16 (256MB)
__device__ float   g_tmin[NTOK * NTILE];       // per-(token,tile) approx min
__device__ float   g_esq[VN];
__device__ int     g_idx[NTOK];

// ---------------- PTX helpers ----------------
static __device__ __forceinline__ uint32_t smem_u32(const void* p) {
    uint32_t a;
    asm("{ .reg .u64 t; cvta.to.shared.u64 t, %1; cvt.u32.u64 %0, t; }" : "=r"(a) : "l"(p));
    return a;
}
static __device__ __forceinline__ void cp16(uint32_t dst, const void* src) {
    asm volatile("cp.async.cg.shared.global [%0], [%1], 16;" :: "r"(dst), "l"(src));
}
#define CP_COMMIT() asm volatile("cp.async.commit_group;" ::: "memory")
#define CP_WAIT(n)  asm volatile("cp.async.wait_group %0;" :: "n"(n) : "memory")

static __device__ __forceinline__ void ldsm4(uint32_t* r, uint32_t addr) {
    asm volatile("ldmatrix.sync.aligned.m8n8.x4.shared.b16 {%0,%1,%2,%3}, [%4];"
        : "=r"(r[0]), "=r"(r[1]), "=r"(r[2]), "=r"(r[3]) : "r"(addr));
}
static __device__ __forceinline__ void mma16816(float* d, const uint32_t* a,
                                                uint32_t b0, uint32_t b1) {
    asm volatile("mma.sync.aligned.m16n8k16.row.col.f32.bf16.bf16.f32 "
        "{%0,%1,%2,%3}, {%4,%5,%6,%7}, {%8,%9}, {%0,%1,%2,%3};"
        : "+f"(d[0]), "+f"(d[1]), "+f"(d[2]), "+f"(d[3])
        : "r"(a[0]), "r"(a[1]), "r"(a[2]), "r"(a[3]), "r"(b0), "r"(b1));
}

// ---------------------------------------------------------------------------
// K1: transpose x [B,C,HW] -> g_xf/g_xa [N][C]
// ---------------------------------------------------------------------------
__global__ void vq_transpose(const float* __restrict__ x) {
    __shared__ float t[32][33];
    const int b = blockIdx.z, c0 = blockIdx.y * 32, hw0 = blockIdx.x * 32;
    const int tx = threadIdx.x, ty = threadIdx.y;
#pragma unroll
    for (int i = 0; i < 4; i++) {
        int c = c0 + ty + i * 8;
        t[ty + i * 8][tx] = x[((size_t)(b * CC + c) << 10) + hw0 + tx];
    }
    __syncthreads();
#pragma unroll
    for (int i = 0; i < 4; i++) {
        int hw = hw0 + ty + i * 8;
        float v = t[tx][ty + i * 8];
        size_t o = (size_t)(b * HWN + hw) * CC + c0 + tx;
        g_xf[o] = v;
        g_xa[o] = __float2bfloat16(v);
    }
}

// ---------------------------------------------------------------------------
// K2: prep: esq (fp64-acc), codebook bf16
// ---------------------------------------------------------------------------
__global__ void vq_prep(const float* __restrict__ cb) {
    const int v = blockIdx.x * 8 + (threadIdx.x >> 5);
    const int lane = threadIdx.x & 31;
    const float* r = cb + (size_t)v * CC;
    float4 a = *(const float4*)(r + lane * 4);
    float4 b = *(const float4*)(r + 128 + lane * 4);
    __nv_bfloat16* o = g_cbb + (size_t)v * CC;
    o[lane * 4 + 0] = __float2bfloat16(a.x);
    o[lane * 4 + 1] = __float2bfloat16(a.y);
    o[lane * 4 + 2] = __float2bfloat16(a.z);
    o[lane * 4 + 3] = __float2bfloat16(a.w);
    o[128 + lane * 4 + 0] = __float2bfloat16(b.x);
    o[128 + lane * 4 + 1] = __float2bfloat16(b.y);
    o[128 + lane * 4 + 2] = __float2bfloat16(b.z);
    o[128 + lane * 4 + 3] = __float2bfloat16(b.w);
    double s = (double)a.x * a.x + (double)a.y * a.y + (double)a.z * a.z + (double)a.w * a.w
             + (double)b.x * b.x + (double)b.y * b.y + (double)b.z * b.z + (double)b.w * b.w;
#pragma unroll
    for (int off = 16; off > 0; off >>= 1)
        s += __shfl_xor_sync(0xffffffffu, s, off);
    if (lane == 0) g_esq[v] = (float)s;
}

// ---------------------------------------------------------------------------
// K3: bf16 mma.sync GEMM (128x128 tile) — R4-proven mainloop —
//     epilogue: fp16 dist dump + per-(token,tile) min (no atomics)
// ---------------------------------------------------------------------------
__global__ void __launch_bounds__(256) vq_gemm() {
    extern __shared__ char smem[];
    const uint32_t sb = smem_u32(smem);
    float* se = (float*)(smem + SM_SE);

    const int tid  = threadIdx.x;
    const int wid  = tid >> 5;
    const int lane = tid & 31;
    const int n0 = blockIdx.x * MT;
    const int v0 = blockIdx.y * VT;

    if (tid < VT) se[tid] = g_esq[v0 + tid];

    const __nv_bfloat16* asrc = g_xa  + (size_t)n0 * CC;
    const __nv_bfloat16* bsrc = g_cbb + (size_t)v0 * CC;

    // ---- async tile loader: chunk kc -> buffer (kc&1) ----
    auto load_chunk = [&](int kc, int buf) {
        const uint32_t sa = sb + SM_A + buf * ABUF;
        const uint32_t sbb = sb + SM_B + buf * ABUF;
#pragma unroll
        for (int i = 0; i < 2; i++) {
            int s = tid + 256 * i;          // 0..511
            int row = s >> 2, c16 = s & 3;  // 16B segment of 64B row
            cp16(sa  + row * ASTR + c16 * 16, asrc + (size_t)row * CC + kc * KCH + c16 * 8);
            cp16(sbb + row * ASTR + c16 * 16, bsrc + (size_t)row * CC + kc * KCH + c16 * 8);
        }
        CP_COMMIT();
    };

    // warp tiling: 4x2 warps, warp tile 32 rows x 64 cols
    const int warp_r = (wid & 3) * 32;
    const int warp_c = (wid >> 2) * 64;

    // per-thread ldmatrix base offsets (bytes, within a buffer)
    const uint32_t aoff = (uint32_t)((warp_r + (lane & 15)) * ASTR + (lane >> 4) * 16);
    const uint32_t boff = (uint32_t)((warp_c + (lane & 7) + ((lane >> 4) << 3)) * ASTR
                                     + ((lane >> 3) & 1) * 16);

    float acc[2][8][4];
#pragma unroll
    for (int mb = 0; mb < 2; mb++)
#pragma unroll
        for (int nb = 0; nb < 8; nb++)
#pragma unroll
            for (int q = 0; q < 4; q++) acc[mb][nb][q] = 0.0f;

    load_chunk(0, 0);

    for (int kc = 0; kc < NCHUNK; kc++) {
        if (kc + 1 < NCHUNK) load_chunk(kc + 1, (kc + 1) & 1);
        if (kc + 1 < NCHUNK) { CP_WAIT(1); } else { CP_WAIT(0); }
        __syncthreads();

        const uint32_t abase = sb + SM_A + (kc & 1) * ABUF + aoff;
        const uint32_t bbase = sb + SM_B + (kc & 1) * ABUF + boff;
#pragma unroll
        for (int ks = 0; ks < 2; ks++) {
            uint32_t af[2][4];
            ldsm4(af[0], abase + ks * 32);
            ldsm4(af[1], abase + 16 * ASTR + ks * 32);
            uint32_t bfr[4][4];
#pragma unroll
            for (int p = 0; p < 4; p++)
                ldsm4(bfr[p], bbase + p * 16 * ASTR + ks * 32);
#pragma unroll
            for (int mb = 0; mb < 2; mb++)
#pragma unroll
                for (int p = 0; p < 4; p++) {
                    mma16816(acc[mb][2 * p],     af[mb], bfr[p][0], bfr[p][1]);
                    mma16816(acc[mb][2 * p + 1], af[mb], bfr[p][2], bfr[p][3]);
                }
        }
        __syncthreads();
    }

    // ---- stage dist = esq - 2*dot as fp16 (stride SST kills conflicts) ----
    __half2* stage = (__half2*)(smem + SM_A);
#pragma unroll
    for (int mb = 0; mb < 2; mb++)
#pragma unroll
        for (int nb = 0; nb < 8; nb++) {
            int r0 = warp_r + mb * 16 + (lane >> 2);
            int c0 = warp_c + nb * 8 + (lane & 3) * 2;
            float e0 = se[c0], e1 = se[c0 + 1];
            stage[(r0 * SST + c0) >> 1] = __floats2half2_rn(
                fmaf(-2.0f, acc[mb][nb][0], e0), fmaf(-2.0f, acc[mb][nb][1], e1));
            stage[((r0 + 8) * SST + c0) >> 1] = __floats2half2_rn(
                fmaf(-2.0f, acc[mb][nb][2], e0), fmaf(-2.0f, acc[mb][nb][3], e1));
        }
    __syncthreads();

    // ---- per-row tile min + coalesced dump. warp w -> rows w*16..w*16+15 ----
    const __half* stg = (const __half*)(smem + SM_A);
#pragma unroll
    for (int r16 = 0; r16 < 16; r16++) {
        const int row = wid * 16 + r16;
        uint2 raw = *(const uint2*)(stg + row * SST + lane * 4);
        float2 f0 = __half22float2(*(__half2*)&raw.x);
        float2 f1 = __half22float2(*(__half2*)&raw.y);
        float bd = fminf(fminf(f0.x, f0.y), fminf(f1.x, f1.y));
#pragma unroll
        for (int off = 16; off > 0; off >>= 1)
            bd = fminf(bd, __shfl_xor_sync(0xffffffffu, bd, off));
        if (lane == 0) g_tmin[(n0 + row) * NTILE + blockIdx.y] = bd;
        *(uint2*)(g_dist + (size_t)(n0 + row) * VN + v0 + lane * 4) = raw;
    }
}

// ---------------------------------------------------------------------------
// K4: hierarchical scan: tile-min prune -> targeted fp16 read -> exact rescore
// ---------------------------------------------------------------------------
#define MARGIN 6.0f
__global__ void __launch_bounds__(256) vq_scan(const float* __restrict__ cb) {
    const int tid = threadIdx.x;
    const int wid = tid >> 5, lane = tid & 31;
    const int n = blockIdx.x * 8 + wid;

    // global approx min from tile mins
    float m0 = g_tmin[n * NTILE + lane];
    float m1 = g_tmin[n * NTILE + 32 + lane];
    float gm = fminf(m0, m1);
#pragma unroll
    for (int off = 16; off > 0; off >>= 1)
        gm = fminf(gm, __shfl_xor_sync(0xffffffffu, gm, off));
    const float thr = gm + MARGIN;

    float xr[8];
    {
        const float4* xp = (const float4*)(g_xf + (size_t)n * CC + lane * 8);
        float4 a = xp[0], b = xp[1];
        xr[0] = a.x; xr[1] = a.y; xr[2] = a.z; xr[3] = a.w;
        xr[4] = b.x; xr[5] = b.y; xr[6] = b.z; xr[7] = b.w;
    }

    float bestd = 3.4e38f;
    int   bestv = 0x7fffffff;
    const __half* drow = g_dist + (size_t)n * VN;

#pragma unroll
    for (int hf = 0; hf < 2; hf++) {
        float tm = hf ? m1 : m0;
        unsigned tb = __ballot_sync(0xffffffffu, tm <= thr);
        while (tb) {
            int ts = __ffs(tb) - 1;
            tb &= tb - 1;
            const int t = hf * 32 + ts;
            // warp reads this tile's 128 fp16 dists
            uint2 q = *(const uint2*)(drow + t * 128 + lane * 4);
            float2 f0 = __half22float2(*(__half2*)&q.x);
            float2 f1 = __half22float2(*(__half2*)&q.y);
            float dd[4] = {f0.x, f0.y, f1.x, f1.y};
#pragma unroll
            for (int j = 0; j < 4; j++) {
                unsigned bal = __ballot_sync(0xffffffffu, dd[j] <= thr);
                while (bal) {
                    int src = __ffs(bal) - 1;
                    bal &= bal - 1;
                    const int vc = t * 128 + src * 4 + j;
                    // exact fp32 rescore (warp-distributed dot)
                    const float4* ep = (const float4*)(cb + (size_t)vc * CC + lane * 8);
                    float4 ea = ep[0], eb = ep[1];
                    float s = xr[0] * ea.x;
                    s = fmaf(xr[1], ea.y, s); s = fmaf(xr[2], ea.z, s);
                    s = fmaf(xr[3], ea.w, s); s = fmaf(xr[4], eb.x, s);
                    s = fmaf(xr[5], eb.y, s); s = fmaf(xr[6], eb.z, s);
                    s = fmaf(xr[7], eb.w, s);
#pragma unroll
                    for (int off = 16; off > 0; off >>= 1)
                        s += __shfl_xor_sync(0xffffffffu, s, off);
                    float d = fmaf(-2.0f, s, __ldg(&g_esq[vc]));
                    if (d < bestd || (d == bestd && vc < bestv)) { bestd = d; bestv = vc; }
                }
            }
        }
    }
    if (lane == 0) g_idx[n] = bestv;
}

// ---------------------------------------------------------------------------
// K5: gather + transpose back
// ---------------------------------------------------------------------------
__global__ void vq_gather(const float* __restrict__ cb, float* __restrict__ out) {
    __shared__ float t[32][33];
    const int b = blockIdx.z, c0 = blockIdx.y * 32, hw0 = blockIdx.x * 32;
    const int tx = threadIdx.x, ty = threadIdx.y;
#pragma unroll
    for (int i = 0; i < 4; i++) {
        int row = ty + i * 8;
        int code = g_idx[b * HWN + hw0 + row];
        t[row][tx] = cb[(size_t)code * CC + c0 + tx];
    }
    __syncthreads();
#pragma unroll
    for (int i = 0; i < 4; i++) {
        int c = c0 + ty + i * 8;
        out[((size_t)(b * CC + c) << 10) + hw0 + tx] = t[tx][ty + i * 8];
    }
}

// ---------------------------------------------------------------------------
extern "C" void kernel_launch(void* const* d_in, const int* in_sizes, int n_in,
                              void* d_out, int out_size) {
    const float* x  = (const float*)d_in[0];
    const float* cb = (const float*)d_in[1];
    float* out = (float*)d_out;

    cudaFuncSetAttribute(vq_gemm, cudaFuncAttributeMaxDynamicSharedMemorySize, SM_DYN);

    vq_transpose<<<dim3(HWN / 32, CC / 32, BB), dim3(32, 8)>>>(x);
    vq_prep<<<VN / 8, 256>>>(cb);
    vq_gemm<<<dim3(NTOK / MT, VN / VT), 256, SM_DYN>>>();
    vq_scan<<<NTOK / 8, 256>>>(cb);
    vq_gather<<<dim3(HWN / 32, CC / 32, BB), dim3(32, 8)>>>(cb, out);
}

// round 7
// speedup vs baseline: 6.9373x; 1.1309x over previous
#include <cuda_runtime.h>
#include <cuda_bf16.h>
#include <cuda_fp16.h>
#include <cstdint>

// ---------------- problem constants ----------------
#define BB   16
#define CC   256
#define HWN  1024
#define NTOK 16384
#define VN   8192
#define NTILE (VN/128)      // 64 v-tiles per token

// ---------------- GEMM tiling (mma.sync path, sm_100-base safe) ----------
#define MT 128              // tokens per CTA
#define VT 128              // codes per CTA
#define KCH 64              // K per chunk
#define NCHUNK (CC/KCH)     // 4
#define ASTR 144            // smem row stride bytes (128B data + 16 pad; 36w%32=4 -> ldmatrix conflict-free)
#define ABUF (128*ASTR)     // 18432 bytes per A/B buffer
#define SST 136             // stage stride in half elements (272B rows)

// smem layout (bytes): [0,512) esq, [512, 512+2*ABUF) A bufs, then B bufs
#define SM_SE 0
#define SM_A  512
#define SM_B  (512 + 2*ABUF)
#define SM_DYN (512 + 4*ABUF)      // 74240
// epilogue stage (128 x 272B = 34816B) aliases the A/B buffers at SM_A

// ---------------- device scratch (allocation-free) ----------------
__device__ float   g_xf[NTOK * CC];            // x fp32 [N][C]
__device__ __nv_bfloat16 g_xa[NTOK * CC];      // x bf16
__device__ __nv_bfloat16 g_cbb[VN * CC];       // codebook bf16
__device__ __half  g_dist[(size_t)NTOK * VN];  // approx dists fp16 (256MB)
__device__ float   g_tmin[NTOK * NTILE];       // per-(token,tile) approx min
__device__ float   g_esq[VN];
__device__ int     g_idx[NTOK];

// ---------------- PTX helpers ----------------
static __device__ __forceinline__ uint32_t smem_u32(const void* p) {
    uint32_t a;
    asm("{ .reg .u64 t; cvta.to.shared.u64 t, %1; cvt.u32.u64 %0, t; }" : "=r"(a) : "l"(p));
    return a;
}
static __device__ __forceinline__ void cp16(uint32_t dst, const void* src) {
    asm volatile("cp.async.cg.shared.global [%0], [%1], 16;" :: "r"(dst), "l"(src));
}
#define CP_COMMIT() asm volatile("cp.async.commit_group;" ::: "memory")
#define CP_WAIT(n)  asm volatile("cp.async.wait_group %0;" :: "n"(n) : "memory")

static __device__ __forceinline__ void ldsm4(uint32_t* r, uint32_t addr) {
    asm volatile("ldmatrix.sync.aligned.m8n8.x4.shared.b16 {%0,%1,%2,%3}, [%4];"
        : "=r"(r[0]), "=r"(r[1]), "=r"(r[2]), "=r"(r[3]) : "r"(addr));
}
static __device__ __forceinline__ void mma16816(float* d, const uint32_t* a,
                                                uint32_t b0, uint32_t b1) {
    asm volatile("mma.sync.aligned.m16n8k16.row.col.f32.bf16.bf16.f32 "
        "{%0,%1,%2,%3}, {%4,%5,%6,%7}, {%8,%9}, {%0,%1,%2,%3};"
        : "+f"(d[0]), "+f"(d[1]), "+f"(d[2]), "+f"(d[3])
        : "r"(a[0]), "r"(a[1]), "r"(a[2]), "r"(a[3]), "r"(b0), "r"(b1));
}

// ---------------------------------------------------------------------------
// K1: transpose x [B,C,HW] -> g_xf/g_xa [N][C]
// ---------------------------------------------------------------------------
__global__ void vq_transpose(const float* __restrict__ x) {
    __shared__ float t[32][33];
    const int b = blockIdx.z, c0 = blockIdx.y * 32, hw0 = blockIdx.x * 32;
    const int tx = threadIdx.x, ty = threadIdx.y;
#pragma unroll
    for (int i = 0; i < 4; i++) {
        int c = c0 + ty + i * 8;
        t[ty + i * 8][tx] = x[((size_t)(b * CC + c) << 10) + hw0 + tx];
    }
    __syncthreads();
#pragma unroll
    for (int i = 0; i < 4; i++) {
        int hw = hw0 + ty + i * 8;
        float v = t[tx][ty + i * 8];
        size_t o = (size_t)(b * HWN + hw) * CC + c0 + tx;
        g_xf[o] = v;
        g_xa[o] = __float2bfloat16(v);
    }
}

// ---------------------------------------------------------------------------
// K2: prep: esq (fp64-acc), codebook bf16
// ---------------------------------------------------------------------------
__global__ void vq_prep(const float* __restrict__ cb) {
    const int v = blockIdx.x * 8 + (threadIdx.x >> 5);
    const int lane = threadIdx.x & 31;
    const float* r = cb + (size_t)v * CC;
    float4 a = *(const float4*)(r + lane * 4);
    float4 b = *(const float4*)(r + 128 + lane * 4);
    __nv_bfloat16* o = g_cbb + (size_t)v * CC;
    o[lane * 4 + 0] = __float2bfloat16(a.x);
    o[lane * 4 + 1] = __float2bfloat16(a.y);
    o[lane * 4 + 2] = __float2bfloat16(a.z);
    o[lane * 4 + 3] = __float2bfloat16(a.w);
    o[128 + lane * 4 + 0] = __float2bfloat16(b.x);
    o[128 + lane * 4 + 1] = __float2bfloat16(b.y);
    o[128 + lane * 4 + 2] = __float2bfloat16(b.z);
    o[128 + lane * 4 + 3] = __float2bfloat16(b.w);
    double s = (double)a.x * a.x + (double)a.y * a.y + (double)a.z * a.z + (double)a.w * a.w
             + (double)b.x * b.x + (double)b.y * b.y + (double)b.z * b.z + (double)b.w * b.w;
#pragma unroll
    for (int off = 16; off > 0; off >>= 1)
        s += __shfl_xor_sync(0xffffffffu, s, off);
    if (lane == 0) g_esq[v] = (float)s;
}

// ---------------------------------------------------------------------------
// K3: bf16 mma.sync GEMM (128x128 tile), K chunks of 64, 1 sync per chunk.
//     epilogue: fp16 dist dump + per-(token,tile) min (no atomics)
// ---------------------------------------------------------------------------
__global__ void __launch_bounds__(256) vq_gemm() {
    extern __shared__ char smem[];
    const uint32_t sb = smem_u32(smem);
    float* se = (float*)(smem + SM_SE);

    const int tid  = threadIdx.x;
    const int wid  = tid >> 5;
    const int lane = tid & 31;
    const int n0 = blockIdx.x * MT;
    const int v0 = blockIdx.y * VT;

    if (tid < VT) se[tid] = g_esq[v0 + tid];

    const __nv_bfloat16* asrc = g_xa  + (size_t)n0 * CC;
    const __nv_bfloat16* bsrc = g_cbb + (size_t)v0 * CC;

    // ---- async tile loader: chunk kc (64 wide) -> buffer (kc&1) ----
    auto load_chunk = [&](int kc, int buf) {
        const uint32_t sa  = sb + SM_A + buf * ABUF;
        const uint32_t sbb = sb + SM_B + buf * ABUF;
#pragma unroll
        for (int i = 0; i < 4; i++) {
            int s = tid + 256 * i;          // 0..1023
            int row = s >> 3, seg = s & 7;  // 16B segment of 128B row
            cp16(sa  + row * ASTR + seg * 16, asrc + (size_t)row * CC + kc * KCH + seg * 8);
            cp16(sbb + row * ASTR + seg * 16, bsrc + (size_t)row * CC + kc * KCH + seg * 8);
        }
        CP_COMMIT();
    };

    // warp tiling: 4x2 warps, warp tile 32 rows x 64 cols
    const int warp_r = (wid & 3) * 32;
    const int warp_c = (wid >> 2) * 64;

    // per-thread ldmatrix base offsets (bytes, within a buffer)
    const uint32_t aoff = (uint32_t)((warp_r + (lane & 15)) * ASTR + (lane >> 4) * 16);
    const uint32_t boff = (uint32_t)((warp_c + (lane & 7) + ((lane >> 4) << 3)) * ASTR
                                     + ((lane >> 3) & 1) * 16);

    float acc[2][8][4];
#pragma unroll
    for (int mb = 0; mb < 2; mb++)
#pragma unroll
        for (int nb = 0; nb < 8; nb++)
#pragma unroll
            for (int q = 0; q < 4; q++) acc[mb][nb][q] = 0.0f;

    load_chunk(0, 0);

    for (int kc = 0; kc < NCHUNK; kc++) {
        CP_WAIT(0);
        __syncthreads();
        // safe: after the sync, no warp still reads buf (kc+1)&1
        if (kc + 1 < NCHUNK) load_chunk(kc + 1, (kc + 1) & 1);

        const uint32_t abase = sb + SM_A + (kc & 1) * ABUF + aoff;
        const uint32_t bbase = sb + SM_B + (kc & 1) * ABUF + boff;
#pragma unroll
        for (int ks = 0; ks < 4; ks++) {
            uint32_t af[2][4];
            ldsm4(af[0], abase + ks * 32);
            ldsm4(af[1], abase + 16 * ASTR + ks * 32);
            uint32_t bfr[4][4];
#pragma unroll
            for (int p = 0; p < 4; p++)
                ldsm4(bfr[p], bbase + p * 16 * ASTR + ks * 32);
#pragma unroll
            for (int mb = 0; mb < 2; mb++)
#pragma unroll
                for (int p = 0; p < 4; p++) {
                    mma16816(acc[mb][2 * p],     af[mb], bfr[p][0], bfr[p][1]);
                    mma16816(acc[mb][2 * p + 1], af[mb], bfr[p][2], bfr[p][3]);
                }
        }
    }
    __syncthreads();   // before staging (stage aliases buffers)

    // ---- stage dist = esq - 2*dot as fp16 (stride SST kills conflicts) ----
    __half2* stage = (__half2*)(smem + SM_A);
#pragma unroll
    for (int mb = 0; mb < 2; mb++)
#pragma unroll
        for (int nb = 0; nb < 8; nb++) {
            int r0 = warp_r + mb * 16 + (lane >> 2);
            int c0 = warp_c + nb * 8 + (lane & 3) * 2;
            float e0 = se[c0], e1 = se[c0 + 1];
            stage[(r0 * SST + c0) >> 1] = __floats2half2_rn(
                fmaf(-2.0f, acc[mb][nb][0], e0), fmaf(-2.0f, acc[mb][nb][1], e1));
            stage[((r0 + 8) * SST + c0) >> 1] = __floats2half2_rn(
                fmaf(-2.0f, acc[mb][nb][2], e0), fmaf(-2.0f, acc[mb][nb][3], e1));
        }
    __syncthreads();

    // ---- per-row tile min + coalesced dump. warp w -> rows w*16..w*16+15 ----
    const __half* stg = (const __half*)(smem + SM_A);
#pragma unroll
    for (int r16 = 0; r16 < 16; r16++) {
        const int row = wid * 16 + r16;
        uint2 raw = *(const uint2*)(stg + row * SST + lane * 4);
        float2 f0 = __half22float2(*(__half2*)&raw.x);
        float2 f1 = __half22float2(*(__half2*)&raw.y);
        float bd = fminf(fminf(f0.x, f0.y), fminf(f1.x, f1.y));
#pragma unroll
        for (int off = 16; off > 0; off >>= 1)
            bd = fminf(bd, __shfl_xor_sync(0xffffffffu, bd, off));
        if (lane == 0) g_tmin[(n0 + row) * NTILE + blockIdx.y] = bd;
        *(uint2*)(g_dist + (size_t)(n0 + row) * VN + v0 + lane * 4) = raw;
    }
}

// ---------------------------------------------------------------------------
// K4: hierarchical scan: tile-min prune -> targeted fp16 read -> exact rescore
// ---------------------------------------------------------------------------
#define MARGIN 6.0f
__global__ void __launch_bounds__(256) vq_scan(const float* __restrict__ cb) {
    const int tid = threadIdx.x;
    const int wid = tid >> 5, lane = tid & 31;
    const int n = blockIdx.x * 8 + wid;

    // global approx min from tile mins
    float m0 = g_tmin[n * NTILE + lane];
    float m1 = g_tmin[n * NTILE + 32 + lane];
    float gm = fminf(m0, m1);
#pragma unroll
    for (int off = 16; off > 0; off >>= 1)
        gm = fminf(gm, __shfl_xor_sync(0xffffffffu, gm, off));
    const float thr = gm + MARGIN;

    float xr[8];
    {
        const float4* xp = (const float4*)(g_xf + (size_t)n * CC + lane * 8);
        float4 a = xp[0], b = xp[1];
        xr[0] = a.x; xr[1] = a.y; xr[2] = a.z; xr[3] = a.w;
        xr[4] = b.x; xr[5] = b.y; xr[6] = b.z; xr[7] = b.w;
    }

    float bestd = 3.4e38f;
    int   bestv = 0x7fffffff;
    const __half* drow = g_dist + (size_t)n * VN;

#pragma unroll
    for (int hf = 0; hf < 2; hf++) {
        float tm = hf ? m1 : m0;
        unsigned tb = __ballot_sync(0xffffffffu, tm <= thr);
        while (tb) {
            int ts = __ffs(tb) - 1;
            tb &= tb - 1;
            const int t = hf * 32 + ts;
            // warp reads this tile's 128 fp16 dists
            uint2 q = *(const uint2*)(drow + t * 128 + lane * 4);
            float2 f0 = __half22float2(*(__half2*)&q.x);
            float2 f1 = __half22float2(*(__half2*)&q.y);
            float dd[4] = {f0.x, f0.y, f1.x, f1.y};
#pragma unroll
            for (int j = 0; j < 4; j++) {
                unsigned bal = __ballot_sync(0xffffffffu, dd[j] <= thr);
                while (bal) {
                    int src = __ffs(bal) - 1;
                    bal &= bal - 1;
                    const int vc = t * 128 + src * 4 + j;
                    // exact fp32 rescore (warp-distributed dot)
                    const float4* ep = (const float4*)(cb + (size_t)vc * CC + lane * 8);
                    float4 ea = ep[0], eb = ep[1];
                    float s = xr[0] * ea.x;
                    s = fmaf(xr[1], ea.y, s); s = fmaf(xr[2], ea.z, s);
                    s = fmaf(xr[3], ea.w, s); s = fmaf(xr[4], eb.x, s);
                    s = fmaf(xr[5], eb.y, s); s = fmaf(xr[6], eb.z, s);
                    s = fmaf(xr[7], eb.w, s);
#pragma unroll
                    for (int off = 16; off > 0; off >>= 1)
                        s += __shfl_xor_sync(0xffffffffu, s, off);
                    float d = fmaf(-2.0f, s, __ldg(&g_esq[vc]));
                    if (d < bestd || (d == bestd && vc < bestv)) { bestd = d; bestv = vc; }
                }
            }
        }
    }
    if (lane == 0) g_idx[n] = bestv;
}

// ---------------------------------------------------------------------------
// K5: gather + transpose back
// ---------------------------------------------------------------------------
__global__ void vq_gather(const float* __restrict__ cb, float* __restrict__ out) {
    __shared__ float t[32][33];
    const int b = blockIdx.z, c0 = blockIdx.y * 32, hw0 = blockIdx.x * 32;
    const int tx = threadIdx.x, ty = threadIdx.y;
#pragma unroll
    for (int i = 0; i < 4; i++) {
        int row = ty + i * 8;
        int code = g_idx[b * HWN + hw0 + row];
        t[row][tx] = cb[(size_t)code * CC + c0 + tx];
    }
    __syncthreads();
#pragma unroll
    for (int i = 0; i < 4; i++) {
        int c = c0 + ty + i * 8;
        out[((size_t)(b * CC + c) << 10) + hw0 + tx] = t[tx][ty + i * 8];
    }
}

// ---------------------------------------------------------------------------
extern "C" void kernel_launch(void* const* d_in, const int* in_sizes, int n_in,
                              void* d_out, int out_size) {
    const float* x  = (const float*)d_in[0];
    const float* cb = (const float*)d_in[1];
    float* out = (float*)d_out;

    cudaFuncSetAttribute(vq_gemm, cudaFuncAttributeMaxDynamicSharedMemorySize, SM_DYN);

    vq_transpose<<<dim3(HWN / 32, CC / 32, BB), dim3(32, 8)>>>(x);
    vq_prep<<<VN / 8, 256>>>(cb);
    vq_gemm<<<dim3(NTOK / MT, VN / VT), 256, SM_DYN>>>();
    vq_scan<<<NTOK / 8, 256>>>(cb);
    vq_gather<<<dim3(HWN / 32, CC / 32, BB), dim3(32, 8)>>>(cb, out);
}